// round 16
// baseline (speedup 1.0000x reference)
#include <cuda_runtime.h>
#include <cstdint>

#define HH 256
#define WW 256
#define NUM_CURVES 256
#define GPER 64                            /* 2 beziers * 32 samples */
#define NGAUSS (NUM_CURVES*GPER)           /* 16384 */
#define LOG2E 1.4426950408889634f
#define NTILE 1024                         /* 32 x 32 tiles of 8x8 px */
#define MASKW (NGAUSS/32)                  /* 512 words per tile */
#define NSEG 4
#define SEGW (MASKW/NSEG)                  /* 128 words per segment */
#define CAP 512                            /* staged survivors per chunk */
#define CUT 12.5f                          /* cutoff: a >= exp(-12.5) ~ 3.7e-6 */

// ---- static scratch (zero at load; mask+cnt re-zeroed in-kernel each run) ----
__device__ float4   d_gA[NGAUSS];            // mx, my, qa, qb
__device__ float4   d_gB[NGAUSS];            // qc, log2(alpha), cr, cg
__device__ float    d_gCb[NGAUSS];           // cb
__device__ uint32_t d_mask[NTILE*MASKW];     // per-tile visibility bitmask
__device__ float4   d_part[NSEG*NTILE*64];   // per (seg,tile,px): rgb, T
__device__ unsigned d_cnt[NTILE];            // tile join counters (self-resetting)

__device__ __forceinline__ float ex2a(float x) {
    float r; asm("ex2.approx.f32 %0, %1;" : "=f"(r) : "f"(x)); return r;
}
__device__ __forceinline__ float lg2a(float x) {
    float r; asm("lg2.approx.f32 %0, %1;" : "=f"(r) : "f"(x)); return r;
}
__device__ __forceinline__ float rcpa(float x) {
    float r; asm("rcp.approx.f32 %0, %1;" : "=f"(r) : "f"(x)); return r;
}
__device__ __forceinline__ float sigm(float x) {
    return rcpa(1.0f + ex2a(-LOG2E * x));
}

// ---------------------------------------------------------------------------
// K1: one warp per curve (proven shape). Vectorized loads + MUFU math.
// ---------------------------------------------------------------------------
__global__ void __launch_bounds__(32)
k_build(const float* __restrict__ ctrl,
        const float* __restrict__ fdc,
        const float* __restrict__ chol,
        const float* __restrict__ opac,
        const float* __restrict__ depth)
{
    int lane = threadIdx.x;
    int ci   = blockIdx.x;

    const float4* cb4 = reinterpret_cast<const float4*>(ctrl + ci * 20);
    float4 v0 = __ldg(&cb4[0]);
    float4 v1 = __ldg(&cb4[1]);
    float4 v2 = __ldg(&cb4[2]);
    float4 v3 = __ldg(&cb4[3]);
    float4 v4 = __ldg(&cb4[4]);

    const float4* dp4 = reinterpret_cast<const float4*>(depth);
    float4 dA = __ldg(&dp4[lane*2]);
    float4 dB = __ldg(&dp4[lane*2+1]);

    float d   = __ldg(&depth[ci]);
    float ch0 = __ldg(&chol[3*ci+0]);
    float ch1 = __ldg(&chol[3*ci+1]);
    float ch2 = __ldg(&chol[3*ci+2]);
    float op  = __ldg(&opac[ci]);
    float f0  = __ldg(&fdc[3*ci+0]);
    float f1  = __ldg(&fdc[3*ci+1]);
    float f2  = __ldg(&fdc[3*ci+2]);

    // --- stable depth rank ---
    int j0 = lane * 8;
    int partial = 0;
    {
        const float* dv = &dA.x;
        #pragma unroll
        for (int jj = 0; jj < 4; ++jj) {
            float dj = dv[jj];
            int j = j0 + jj;
            partial += (dj < d) || (dj == d && j < ci);
        }
        const float* dw = &dB.x;
        #pragma unroll
        for (int jj = 0; jj < 4; ++jj) {
            float dj = dw[jj];
            int j = j0 + 4 + jj;
            partial += (dj < d) || (dj == d && j < ci);
        }
    }
    partial += __shfl_xor_sync(0xffffffffu, partial, 16);
    partial += __shfl_xor_sync(0xffffffffu, partial, 8);
    partial += __shfl_xor_sync(0xffffffffu, partial, 4);
    partial += __shfl_xor_sync(0xffffffffu, partial, 2);
    partial += __shfl_xor_sync(0xffffffffu, partial, 1);
    int rank = partial;

    // --- per-curve conic / color / extent ---
    float c0 = ch0 + 0.5f;
    float c1 = ch1;
    float c2 = ch2 + 0.5f;
    float s00 = c0*c0;
    float s01 = c0*c1;
    float s11 = c1*c1 + c2*c2;
    float inv = rcpa(s00*s11 - s01*s01);

    float al  = sigm(op);
    float l2a = lg2a(al);
    float Q = fmaxf(2.0f * fmaf(0.6931471805599453f, l2a, CUT), 0.0f);
    float ex = sqrtf(Q * s00);
    float ey = sqrtf(Q * s11);

    float cpA = -0.5f*LOG2E*( s11*inv);
    float cpB =       -LOG2E*(-s01*inv);
    float cpC = -0.5f*LOG2E*( s00*inv);
    float colr = sigm(f0);
    float colg = sigm(f1);
    float colb = sigm(f2);

    // --- Bernstein weights (sample = lane) ---
    float tt = 0.007f + (float)lane * (0.986f / 31.0f);
    float u  = 1.0f - tt;
    float t2 = tt*tt, t3 = t2*tt, t4 = t2*t2, t5 = t4*tt;
    float u2 = u*u,   u3 = u2*u,  u4 = u2*u2, u5 = u4*u;
    float w0 = u5, w1 = 5.0f*tt*u4, w2 = 10.0f*t2*u3;
    float w3 = 10.0f*t3*u2, w4 = 5.0f*t4*u, w5 = t5;

    float cpx[10], cpy[10];
    cpx[0]=v0.x; cpy[0]=v0.y; cpx[1]=v0.z; cpy[1]=v0.w;
    cpx[2]=v1.x; cpy[2]=v1.y; cpx[3]=v1.z; cpy[3]=v1.w;
    cpx[4]=v2.x; cpy[4]=v2.y; cpx[5]=v2.z; cpy[5]=v2.w;
    cpx[6]=v3.x; cpy[6]=v3.y; cpx[7]=v3.z; cpy[7]=v3.w;
    cpx[8]=v4.x; cpy[8]=v4.y; cpx[9]=v4.z; cpy[9]=v4.w;

    #pragma unroll
    for (int k = 0; k < 2; ++k) {
        int i0 = k*5;
        int a5 = k ? 0 : 5;
        float px = w0*cpx[i0] + w1*cpx[i0+1] + w2*cpx[i0+2]
                 + w3*cpx[i0+3] + w4*cpx[i0+4] + w5*cpx[a5];
        float py = w0*cpy[i0] + w1*cpy[i0+1] + w2*cpy[i0+2]
                 + w3*cpy[i0+3] + w4*cpy[i0+4] + w5*cpy[a5];
        float mx = (float)WW * sigm(2.0f*px);
        float my = (float)HH * sigm(2.0f*py);

        int slot = rank*64 + k*32 + lane;
        d_gA[slot]  = make_float4(mx, my, cpA, cpB);
        d_gB[slot]  = make_float4(cpC, l2a, colr, colg);
        d_gCb[slot] = colb;

        int xlo = max(0,  (int)ceilf ((mx - ex - 8.0f) * 0.125f - 1e-4f));
        int xhi = min(31, (int)floorf((mx + ex)        * 0.125f + 1e-4f));
        int ylo = max(0,  (int)ceilf ((my - ey - 8.0f) * 0.125f - 1e-4f));
        int yhi = min(31, (int)floorf((my + ey)        * 0.125f + 1e-4f));
        if (xlo <= xhi && ylo <= yhi) {
            uint32_t bit  = 1u << (slot & 31);
            int      word = slot >> 5;
            for (int ty = ylo; ty <= yhi; ++ty)
                for (int tx = xlo; tx <= xhi; ++tx)
                    atomicOr(&d_mask[(ty*32 + tx)*MASKW + word], bit);
        }
    }
}

// ---------------------------------------------------------------------------
// K2: depth-segmented compositing with FUSED per-tile combine.
// grid = (1024 tiles, 4 segments), 64 threads.
// seg 1..3: write partial, release-arrive on d_cnt[tile].
// seg 0:    acquire-wait for 3 arrivals, combine (own partial in regs),
//           write image, clear tile mask, reset counter.
// ---------------------------------------------------------------------------
__global__ void __launch_bounds__(64)
k_render(const float* __restrict__ bgp, float* __restrict__ out)
{
    __shared__ float4 shQ1[CAP];   // qa, qb, qc, D
    __shared__ float4 shQ2[CAP];   // E, F, cr, cg
    __shared__ float  shCb[CAP];
    __shared__ int    sW[2];

    int t    = threadIdx.x;
    int lane = t & 31;
    int wid  = t >> 5;
    int tile = blockIdx.x;
    int seg  = blockIdx.y;
    int tx8  = tile & 31;
    int ty8  = tile >> 5;
    float cx = (float)(tx8*8) + 4.0f;
    float cy = (float)(ty8*8) + 4.0f;
    float p  = (float)(t & 7) - 3.5f;
    float q  = (float)(t >> 3) - 3.5f;

    const uint32_t* mw = d_mask + (size_t)tile*MASKW + seg*SEGW + t*2;
    uint32_t m0 = mw[0];
    uint32_t m1 = mw[1];
    int c = __popc(m0) + __popc(m1);

    int incl = c;
    #pragma unroll
    for (int d = 1; d < 32; d <<= 1) {
        int v = __shfl_up_sync(0xffffffffu, incl, d);
        if (lane >= d) incl += v;
    }
    if (lane == 31) sW[wid] = incl;
    __syncthreads();
    int w0s = sW[0];
    int total = w0s + sW[1];
    int off = (wid ? w0s : 0) + incl - c;

    float T = 1.0f, cr = 0.0f, cg = 0.0f, cb = 0.0f;
    int slotBase = seg*SEGW*32 + t*64;

    for (int base = 0; base < total; base += CAP) {
        if (base > 0 && __syncthreads_and(T < 1e-4f)) break;
        int lim = min(base + CAP, total);

        if (off < lim && off + c > base) {
            int o = off;
            uint32_t mm = m0;
            int sb = slotBase;
            #pragma unroll
            for (int w = 0; w < 2; ++w) {
                while (mm) {
                    int b = __ffs(mm) - 1;
                    mm &= mm - 1;
                    if (o >= base && o < lim) {
                        int j = o - base;
                        int slot = sb + b;
                        float4 A = d_gA[slot];
                        float4 B = d_gB[slot];
                        float ax = A.x - cx;
                        float ay = A.y - cy;
                        float qa = A.z, qb = A.w, qc = B.x;
                        float D = -(2.0f*qa*ax + qb*ay);
                        float E = -(2.0f*qc*ay + qb*ax);
                        float F = fmaf(qa*ax, ax, fmaf(qb*ax, ay,
                                  fmaf(qc*ay, ay, B.y)));
                        shQ1[j] = make_float4(qa, qb, qc, D);
                        shQ2[j] = make_float4(E, F, B.z, B.w);
                        shCb[j] = d_gCb[slot];
                    }
                    ++o;
                }
                mm = m1;
                sb = slotBase + 32;
            }
        }
        __syncthreads();

        int n = lim - base;
        int i = 0;
        while (i < n) {
            int ie = min(i + 64, n);
            if (T >= 1e-4f) {
                #pragma unroll 2
                for (; i < ie; ++i) {
                    float4 Q1 = shQ1[i];
                    float4 Q2 = shQ2[i];
                    float h1 = fmaf(Q1.y, q, Q1.w);
                    float uu = fmaf(Q1.x, p, h1);
                    float vv = fmaf(Q1.z, q, Q2.x);
                    float h2 = fmaf(q, vv, Q2.y);
                    float e  = fmaf(p, uu, h2);
                    float a;
                    asm("ex2.approx.f32 %0, %1;" : "=f"(a) : "f"(e));
                    float w = a * T;
                    cr = fmaf(w, Q2.z, cr);
                    cg = fmaf(w, Q2.w, cg);
                    cb = fmaf(w, shCb[i], cb);
                    T  = fmaf(-a, T, T);
                }
            } else {
                i = ie;
            }
            if (__all_sync(0xffffffffu, T < 1e-4f)) i = n;
        }
        __syncthreads();
    }

    if (seg != 0) {
        // publish partial, then release-arrive (block-level release idiom)
        d_part[(seg*NTILE + tile)*64 + t] = make_float4(cr, cg, cb, T);
        __syncthreads();
        if (t == 0) {
            unsigned* cnt = &d_cnt[tile];
            asm volatile("red.add.release.gpu.global.u32 [%0], 1;"
                         :: "l"(cnt) : "memory");
        }
        return;
    }

    // --- seg 0: wait for the other 3 segments of this tile ---
    if (t == 0) {
        unsigned* cnt = &d_cnt[tile];
        unsigned v;
        do {
            asm volatile("ld.acquire.gpu.global.u32 %0, [%1];"
                         : "=r"(v) : "l"(cnt) : "memory");
            if (v < NSEG-1) __nanosleep(64);
        } while (v < NSEG-1);
    }
    __syncthreads();

    // combine: own partial (front-most) is in registers
    float Tc = T, fr = cr, fg = cg, fb = cb;
    #pragma unroll
    for (int s = 1; s < NSEG; ++s) {
        float4 pp = d_part[(s*NTILE + tile)*64 + t];
        fr = fmaf(Tc, pp.x, fr);
        fg = fmaf(Tc, pp.y, fg);
        fb = fmaf(Tc, pp.z, fb);
        Tc *= pp.w;
    }

    float b0 = __ldg(&bgp[0]), b1 = __ldg(&bgp[1]), b2 = __ldg(&bgp[2]);
    fr = fminf(fmaxf(fmaf(Tc, b0, fr), 0.0f), 1.0f);
    fg = fminf(fmaxf(fmaf(Tc, b1, fg), 0.0f), 1.0f);
    fb = fminf(fmaxf(fmaf(Tc, b2, fb), 0.0f), 1.0f);

    int x = tx8*8 + (t & 7);
    int y = ty8*8 + (t >> 3);
    int o = (y*WW + x) * 3;
    out[o+0] = fr;
    out[o+1] = fg;
    out[o+2] = fb;

    // housekeeping for next graph replay: clear tile mask + reset counter
    uint4* mz = reinterpret_cast<uint4*>(d_mask + (size_t)tile*MASKW) + t*2;
    mz[0] = make_uint4(0u, 0u, 0u, 0u);
    mz[1] = make_uint4(0u, 0u, 0u, 0u);
    if (t == 0) d_cnt[tile] = 0;
}

// ---------------------------------------------------------------------------
extern "C" void kernel_launch(void* const* d_in, const int* in_sizes, int n_in,
                              void* d_out, int out_size)
{
    const float* ctrl  = (const float*)d_in[0];
    const float* fdc   = (const float*)d_in[1];
    const float* chol  = (const float*)d_in[2];
    const float* opac  = (const float*)d_in[3];
    const float* depth = (const float*)d_in[4];
    const float* bg    = (const float*)d_in[5];
    float* out = (float*)d_out;

    k_build<<<NUM_CURVES, 32>>>(ctrl, fdc, chol, opac, depth);
    k_render<<<dim3(NTILE, NSEG), 64>>>(bg, out);
}

// round 17
// speedup vs baseline: 2.1037x; 2.1037x over previous
#include <cuda_runtime.h>
#include <cstdint>

#define HH 256
#define WW 256
#define NUM_CURVES 256
#define GPER 64                            /* 2 beziers * 32 samples */
#define NGAUSS (NUM_CURVES*GPER)           /* 16384 */
#define LOG2E 1.4426950408889634f
#define NTILE 1024                         /* 32 x 32 tiles of 8x8 px */
#define MASKW (NGAUSS/32)                  /* 512 words per tile */
#define NSEG 4
#define SEGW (MASKW/NSEG)                  /* 128 words per segment */
#define CAP 512                            /* staged survivors per chunk */
#define CUT 12.5f                          /* cutoff: a >= exp(-12.5) ~ 3.7e-6 */

// ---- static scratch (d_mask zero at load; re-zeroed by k_combine each run) ----
__device__ float4   d_gA[NGAUSS];            // mx, my, qa, qb
__device__ float4   d_gB[NGAUSS];            // qc, log2(alpha), cr, cg
__device__ float    d_gCb[NGAUSS];           // cb
__device__ uint32_t d_mask[NTILE*MASKW];     // per-tile visibility bitmask
__device__ float4   d_part[NSEG*NTILE*64];   // per (seg,tile,px): rgb, T

__device__ __forceinline__ float ex2a(float x) {
    float r; asm("ex2.approx.f32 %0, %1;" : "=f"(r) : "f"(x)); return r;
}
__device__ __forceinline__ float lg2a(float x) {
    float r; asm("lg2.approx.f32 %0, %1;" : "=f"(r) : "f"(x)); return r;
}
__device__ __forceinline__ float rcpa(float x) {
    float r; asm("rcp.approx.f32 %0, %1;" : "=f"(r) : "f"(x)); return r;
}
__device__ __forceinline__ float sigm(float x) {
    return rcpa(1.0f + ex2a(-LOG2E * x));
}

// ---------------------------------------------------------------------------
// K1: one warp per curve (proven 4.8us shape). Vectorized loads + MUFU math.
// ---------------------------------------------------------------------------
__global__ void __launch_bounds__(32)
k_build(const float* __restrict__ ctrl,
        const float* __restrict__ fdc,
        const float* __restrict__ chol,
        const float* __restrict__ opac,
        const float* __restrict__ depth)
{
    int lane = threadIdx.x;
    int ci   = blockIdx.x;

    const float4* cb4 = reinterpret_cast<const float4*>(ctrl + ci * 20);
    float4 v0 = __ldg(&cb4[0]);
    float4 v1 = __ldg(&cb4[1]);
    float4 v2 = __ldg(&cb4[2]);
    float4 v3 = __ldg(&cb4[3]);
    float4 v4 = __ldg(&cb4[4]);

    const float4* dp4 = reinterpret_cast<const float4*>(depth);
    float4 dA = __ldg(&dp4[lane*2]);
    float4 dB = __ldg(&dp4[lane*2+1]);

    float d   = __ldg(&depth[ci]);
    float ch0 = __ldg(&chol[3*ci+0]);
    float ch1 = __ldg(&chol[3*ci+1]);
    float ch2 = __ldg(&chol[3*ci+2]);
    float op  = __ldg(&opac[ci]);
    float f0  = __ldg(&fdc[3*ci+0]);
    float f1  = __ldg(&fdc[3*ci+1]);
    float f2  = __ldg(&fdc[3*ci+2]);

    // --- stable depth rank ---
    int j0 = lane * 8;
    int partial = 0;
    {
        const float* dv = &dA.x;
        #pragma unroll
        for (int jj = 0; jj < 4; ++jj) {
            float dj = dv[jj];
            int j = j0 + jj;
            partial += (dj < d) || (dj == d && j < ci);
        }
        const float* dw = &dB.x;
        #pragma unroll
        for (int jj = 0; jj < 4; ++jj) {
            float dj = dw[jj];
            int j = j0 + 4 + jj;
            partial += (dj < d) || (dj == d && j < ci);
        }
    }
    partial += __shfl_xor_sync(0xffffffffu, partial, 16);
    partial += __shfl_xor_sync(0xffffffffu, partial, 8);
    partial += __shfl_xor_sync(0xffffffffu, partial, 4);
    partial += __shfl_xor_sync(0xffffffffu, partial, 2);
    partial += __shfl_xor_sync(0xffffffffu, partial, 1);
    int rank = partial;

    // --- per-curve conic / color / extent ---
    float c0 = ch0 + 0.5f;
    float c1 = ch1;
    float c2 = ch2 + 0.5f;
    float s00 = c0*c0;
    float s01 = c0*c1;
    float s11 = c1*c1 + c2*c2;
    float inv = rcpa(s00*s11 - s01*s01);

    float al  = sigm(op);
    float l2a = lg2a(al);
    float Q = fmaxf(2.0f * fmaf(0.6931471805599453f, l2a, CUT), 0.0f);
    float ex = sqrtf(Q * s00);
    float ey = sqrtf(Q * s11);

    float cpA = -0.5f*LOG2E*( s11*inv);
    float cpB =       -LOG2E*(-s01*inv);
    float cpC = -0.5f*LOG2E*( s00*inv);
    float colr = sigm(f0);
    float colg = sigm(f1);
    float colb = sigm(f2);

    // --- Bernstein weights (sample = lane) ---
    float tt = 0.007f + (float)lane * (0.986f / 31.0f);
    float u  = 1.0f - tt;
    float t2 = tt*tt, t3 = t2*tt, t4 = t2*t2, t5 = t4*tt;
    float u2 = u*u,   u3 = u2*u,  u4 = u2*u2, u5 = u4*u;
    float w0 = u5, w1 = 5.0f*tt*u4, w2 = 10.0f*t2*u3;
    float w3 = 10.0f*t3*u2, w4 = 5.0f*t4*u, w5 = t5;

    float cpx[10], cpy[10];
    cpx[0]=v0.x; cpy[0]=v0.y; cpx[1]=v0.z; cpy[1]=v0.w;
    cpx[2]=v1.x; cpy[2]=v1.y; cpx[3]=v1.z; cpy[3]=v1.w;
    cpx[4]=v2.x; cpy[4]=v2.y; cpx[5]=v2.z; cpy[5]=v2.w;
    cpx[6]=v3.x; cpy[6]=v3.y; cpx[7]=v3.z; cpy[7]=v3.w;
    cpx[8]=v4.x; cpy[8]=v4.y; cpx[9]=v4.z; cpy[9]=v4.w;

    #pragma unroll
    for (int k = 0; k < 2; ++k) {
        int i0 = k*5;
        int a5 = k ? 0 : 5;
        float px = w0*cpx[i0] + w1*cpx[i0+1] + w2*cpx[i0+2]
                 + w3*cpx[i0+3] + w4*cpx[i0+4] + w5*cpx[a5];
        float py = w0*cpy[i0] + w1*cpy[i0+1] + w2*cpy[i0+2]
                 + w3*cpy[i0+3] + w4*cpy[i0+4] + w5*cpy[a5];
        float mx = (float)WW * sigm(2.0f*px);
        float my = (float)HH * sigm(2.0f*py);

        int slot = rank*64 + k*32 + lane;
        d_gA[slot]  = make_float4(mx, my, cpA, cpB);
        d_gB[slot]  = make_float4(cpC, l2a, colr, colg);
        d_gCb[slot] = colb;

        int xlo = max(0,  (int)ceilf ((mx - ex - 8.0f) * 0.125f - 1e-4f));
        int xhi = min(31, (int)floorf((mx + ex)        * 0.125f + 1e-4f));
        int ylo = max(0,  (int)ceilf ((my - ey - 8.0f) * 0.125f - 1e-4f));
        int yhi = min(31, (int)floorf((my + ey)        * 0.125f + 1e-4f));
        if (xlo <= xhi && ylo <= yhi) {
            uint32_t bit  = 1u << (slot & 31);
            int      word = slot >> 5;
            for (int ty = ylo; ty <= yhi; ++ty)
                for (int tx = xlo; tx <= xhi; ++tx)
                    atomicOr(&d_mask[(ty*32 + tx)*MASKW + word], bit);
        }
    }
}

// ---------------------------------------------------------------------------
// K2: depth-segmented per-tile compositing (PDL: grid launches early,
// waits on k_build via cudaGridDependencySynchronize before reading).
// ---------------------------------------------------------------------------
__global__ void __launch_bounds__(64)
k_render()
{
    __shared__ float4 shQ1[CAP];   // qa, qb, qc, D
    __shared__ float4 shQ2[CAP];   // E, F, cr, cg
    __shared__ float  shCb[CAP];
    __shared__ int    sW[2];

    int t    = threadIdx.x;
    int lane = t & 31;
    int wid  = t >> 5;
    int tile = blockIdx.x;
    int seg  = blockIdx.y;
    int tx8  = tile & 31;
    int ty8  = tile >> 5;
    float cx = (float)(tx8*8) + 4.0f;
    float cy = (float)(ty8*8) + 4.0f;
    float p  = (float)(t & 7) - 3.5f;
    float q  = (float)(t >> 3) - 3.5f;
    const uint32_t* mw = d_mask + (size_t)tile*MASKW + seg*SEGW + t*2;
    int slotBase = seg*SEGW*32 + t*64;

    // wait for k_build's writes to be visible (PDL dependency)
    cudaGridDependencySynchronize();

    uint32_t m0 = mw[0];
    uint32_t m1 = mw[1];
    int c = __popc(m0) + __popc(m1);

    int incl = c;
    #pragma unroll
    for (int d = 1; d < 32; d <<= 1) {
        int v = __shfl_up_sync(0xffffffffu, incl, d);
        if (lane >= d) incl += v;
    }
    if (lane == 31) sW[wid] = incl;
    __syncthreads();
    int w0s = sW[0];
    int total = w0s + sW[1];
    int off = (wid ? w0s : 0) + incl - c;

    float T = 1.0f, cr = 0.0f, cg = 0.0f, cb = 0.0f;

    for (int base = 0; base < total; base += CAP) {
        if (base > 0 && __syncthreads_and(T < 1e-4f)) break;
        int lim = min(base + CAP, total);

        if (off < lim && off + c > base) {
            int o = off;
            uint32_t mm = m0;
            int sb = slotBase;
            #pragma unroll
            for (int w = 0; w < 2; ++w) {
                while (mm) {
                    int b = __ffs(mm) - 1;
                    mm &= mm - 1;
                    if (o >= base && o < lim) {
                        int j = o - base;
                        int slot = sb + b;
                        float4 A = d_gA[slot];
                        float4 B = d_gB[slot];
                        float ax = A.x - cx;
                        float ay = A.y - cy;
                        float qa = A.z, qb = A.w, qc = B.x;
                        float D = -(2.0f*qa*ax + qb*ay);
                        float E = -(2.0f*qc*ay + qb*ax);
                        float F = fmaf(qa*ax, ax, fmaf(qb*ax, ay,
                                  fmaf(qc*ay, ay, B.y)));
                        shQ1[j] = make_float4(qa, qb, qc, D);
                        shQ2[j] = make_float4(E, F, B.z, B.w);
                        shCb[j] = d_gCb[slot];
                    }
                    ++o;
                }
                mm = m1;
                sb = slotBase + 32;
            }
        }
        __syncthreads();

        int n = lim - base;
        int i = 0;
        while (i < n) {
            int ie = min(i + 64, n);
            if (T >= 1e-4f) {
                #pragma unroll 2
                for (; i < ie; ++i) {
                    float4 Q1 = shQ1[i];
                    float4 Q2 = shQ2[i];
                    float h1 = fmaf(Q1.y, q, Q1.w);
                    float uu = fmaf(Q1.x, p, h1);
                    float vv = fmaf(Q1.z, q, Q2.x);
                    float h2 = fmaf(q, vv, Q2.y);
                    float e  = fmaf(p, uu, h2);
                    float a;
                    asm("ex2.approx.f32 %0, %1;" : "=f"(a) : "f"(e));
                    float w = a * T;
                    cr = fmaf(w, Q2.z, cr);
                    cg = fmaf(w, Q2.w, cg);
                    cb = fmaf(w, shCb[i], cb);
                    T  = fmaf(-a, T, T);
                }
            } else {
                i = ie;
            }
            if (__all_sync(0xffffffffu, T < 1e-4f)) i = n;
        }
        __syncthreads();
    }

    d_part[(seg*NTILE + tile)*64 + t] = make_float4(cr, cg, cb, T);
}

// ---------------------------------------------------------------------------
// K3: combine partials (PDL-gated), write output, clear tile mask for replay.
// ---------------------------------------------------------------------------
__global__ void __launch_bounds__(64)
k_combine(const float* __restrict__ bgp, float* __restrict__ out)
{
    int t    = threadIdx.x;
    int tile = blockIdx.x;
    int tx8  = tile & 31;
    int ty8  = tile >> 5;

    cudaGridDependencySynchronize();

    float T = 1.0f, cr = 0.0f, cg = 0.0f, cb = 0.0f;
    #pragma unroll
    for (int s = 0; s < NSEG; ++s) {
        float4 pp = d_part[(s*NTILE + tile)*64 + t];
        cr = fmaf(T, pp.x, cr);
        cg = fmaf(T, pp.y, cg);
        cb = fmaf(T, pp.z, cb);
        T *= pp.w;
    }

    float b0 = bgp[0], b1 = bgp[1], b2 = bgp[2];
    cr = fminf(fmaxf(fmaf(T, b0, cr), 0.0f), 1.0f);
    cg = fminf(fmaxf(fmaf(T, b1, cg), 0.0f), 1.0f);
    cb = fminf(fmaxf(fmaf(T, b2, cb), 0.0f), 1.0f);

    int x = tx8*8 + (t & 7);
    int y = ty8*8 + (t >> 3);
    int o = (y*WW + x) * 3;
    out[o+0] = cr;
    out[o+1] = cg;
    out[o+2] = cb;

    // clear this tile's mask (8 words per thread = 2 x uint4 stores)
    uint4* mz = reinterpret_cast<uint4*>(d_mask + (size_t)tile*MASKW) + t*2;
    mz[0] = make_uint4(0u, 0u, 0u, 0u);
    mz[1] = make_uint4(0u, 0u, 0u, 0u);
}

// ---------------------------------------------------------------------------
extern "C" void kernel_launch(void* const* d_in, const int* in_sizes, int n_in,
                              void* d_out, int out_size)
{
    const float* ctrl  = (const float*)d_in[0];
    const float* fdc   = (const float*)d_in[1];
    const float* chol  = (const float*)d_in[2];
    const float* opac  = (const float*)d_in[3];
    const float* depth = (const float*)d_in[4];
    const float* bg    = (const float*)d_in[5];
    float* out = (float*)d_out;

    k_build<<<NUM_CURVES, 32>>>(ctrl, fdc, chol, opac, depth);

    // k_render with programmatic dependent launch (overlaps k_build tail)
    {
        cudaLaunchConfig_t cfg = {};
        cfg.gridDim  = dim3(NTILE, NSEG, 1);
        cfg.blockDim = dim3(64, 1, 1);
        cudaLaunchAttribute attr[1];
        attr[0].id = cudaLaunchAttributeProgrammaticStreamSerialization;
        attr[0].val.programmaticStreamSerializationAllowed = 1;
        cfg.attrs = attr;
        cfg.numAttrs = 1;
        cudaLaunchKernelEx(&cfg, k_render);
    }

    // k_combine with PDL (overlaps k_render tail)
    {
        cudaLaunchConfig_t cfg = {};
        cfg.gridDim  = dim3(NTILE, 1, 1);
        cfg.blockDim = dim3(64, 1, 1);
        cudaLaunchAttribute attr[1];
        attr[0].id = cudaLaunchAttributeProgrammaticStreamSerialization;
        attr[0].val.programmaticStreamSerializationAllowed = 1;
        cfg.attrs = attr;
        cfg.numAttrs = 1;
        cudaLaunchKernelEx(&cfg, k_combine, bg, out);
    }
}